// round 7
// baseline (speedup 1.0000x reference)
#include <cuda_runtime.h>
#include <cuda_bf16.h>

#define B 2048
#define C 1024
#define TEMP_INV 0.5f
#define EPS_INV 10.0f
#define N_ITERS 20
#define LOSS_SCALE 0.001f
#define PBLK 128            // persistent blocks (all co-resident: < 152 SMs)
#define RPB (B / PBLK)      // 16 rows/cols owned per block

typedef unsigned long long u64;
typedef unsigned int u32;

// ---------------- scratch (device globals; no runtime allocation) -----------
__device__ float g_ps[B * C];
__device__ float g_pt[B * C];
__device__ float g_W [B * B];
__device__ float g_K [B * B];
__device__ float g_b [B];
__device__ float g_lp[B];
__device__ float g_part[PBLK * B];   // per-block partial column sums
__device__ int   g_bar[64];          // one counter per barrier instance

// ---------------- f32x2 helpers ---------------------------------------------
__device__ __forceinline__ u64 addf32x2(u64 a, u64 b) {
    u64 r;
    asm("add.rn.f32x2 %0, %1, %2;" : "=l"(r) : "l"(a), "l"(b));
    return r;
}
__device__ __forceinline__ u64 dupf(float f) {
    u32 u = __float_as_uint(f);
    return (u64)u | ((u64)u << 32);
}
__device__ __forceinline__ float lo32f(u64 v) { return __uint_as_float((u32)v); }
__device__ __forceinline__ float hi32f(u64 v) { return __uint_as_float((u32)(v >> 32)); }

// ---------------- softmax: one block per row (4096 rows) --------------------
__global__ __launch_bounds__(256) void softmax_kernel(const float* __restrict__ ys,
                                                      const float* __restrict__ yt) {
    int row = blockIdx.x;
    const float* src = (row < B) ? (ys + (size_t)row * C) : (yt + (size_t)(row - B) * C);
    float*       dst = (row < B) ? (g_ps + (size_t)row * C) : (g_pt + (size_t)(row - B) * C);
    int tid = threadIdx.x;

    float4 x = ((const float4*)src)[tid];
    x.x *= TEMP_INV; x.y *= TEMP_INV; x.z *= TEMP_INV; x.w *= TEMP_INV;

    __shared__ float smx[8];
    __shared__ float bc;

    float m = fmaxf(fmaxf(x.x, x.y), fmaxf(x.z, x.w));
    #pragma unroll
    for (int o = 16; o > 0; o >>= 1) m = fmaxf(m, __shfl_down_sync(0xffffffffu, m, o));
    int lane = tid & 31, w = tid >> 5;
    if (lane == 0) smx[w] = m;
    __syncthreads();
    if (w == 0) {
        m = (lane < 8) ? smx[lane] : -1e30f;
        #pragma unroll
        for (int o = 4; o > 0; o >>= 1) m = fmaxf(m, __shfl_down_sync(0xffu, m, o));
        if (lane == 0) bc = m;
    }
    __syncthreads();
    m = bc;

    float4 e;
    e.x = __expf(x.x - m); e.y = __expf(x.y - m);
    e.z = __expf(x.z - m); e.w = __expf(x.w - m);
    float s = (e.x + e.y) + (e.z + e.w);

    #pragma unroll
    for (int o = 16; o > 0; o >>= 1) s += __shfl_down_sync(0xffffffffu, s, o);
    __syncthreads();
    if (lane == 0) smx[w] = s;
    __syncthreads();
    if (w == 0) {
        s = (lane < 8) ? smx[lane] : 0.0f;
        #pragma unroll
        for (int o = 4; o > 0; o >>= 1) s += __shfl_down_sync(0xffu, s, o);
        if (lane == 0) bc = s;
    }
    __syncthreads();
    float inv = __fdividef(1.0f, bc);

    e.x *= inv; e.y *= inv; e.z *= inv; e.w *= inv;
    ((float4*)dst)[tid] = e;
}

// zero barrier slots each replay (graph-capture-safe reset)
__global__ void zero_bar_kernel() {
    if (threadIdx.x < 64) g_bar[threadIdx.x] = 0;
}

// ---------------- cdist L1 (f32x2 packed) + K --------------------------------
#define KC   32
#define LDA2 33
#define LDBT 130

__global__ __launch_bounds__(256, 2) void cdist_kernel() {
    __shared__ u64   As2[128 * LDA2];
    __shared__ float BsT[KC * LDBT];

    int bi = blockIdx.y, bj = blockIdx.x;
    int tid = threadIdx.x;
    int tx = tid & 15, ty = tid >> 4;

    const float* Abase = g_ps + (size_t)(bi * 128) * C;
    const float* Bbase = g_pt + (size_t)(bj * 128) * C;

    u64 acc[8][4];
    #pragma unroll
    for (int r = 0; r < 8; r++)
        #pragma unroll
        for (int c = 0; c < 4; c++) acc[r][c] = 0ull;

    for (int k0 = 0; k0 < C; k0 += KC) {
        #pragma unroll
        for (int l = 0; l < 4; l++) {
            int v   = tid + l * 256;
            int row = v >> 3;
            int kq  = (v & 7) << 2;
            float4 a4 = *(const float4*)(Abase + (size_t)row * C + k0 + kq);
            As2[row * LDA2 + kq + 0] = dupf(a4.x);
            As2[row * LDA2 + kq + 1] = dupf(a4.y);
            As2[row * LDA2 + kq + 2] = dupf(a4.z);
            As2[row * LDA2 + kq + 3] = dupf(a4.w);
            float4 b4 = *(const float4*)(Bbase + (size_t)row * C + k0 + kq);
            BsT[(kq + 0) * LDBT + row] = -b4.x;
            BsT[(kq + 1) * LDBT + row] = -b4.y;
            BsT[(kq + 2) * LDBT + row] = -b4.z;
            BsT[(kq + 3) * LDBT + row] = -b4.w;
        }
        __syncthreads();

        #pragma unroll 4
        for (int k = 0; k < KC; k++) {
            u64 b2[4];
            const u64* bp = (const u64*)(BsT + k * LDBT + tx * 8);
            #pragma unroll
            for (int c = 0; c < 4; c++) b2[c] = bp[c];
            #pragma unroll
            for (int r = 0; r < 8; r++) {
                u64 a2 = As2[(ty * 8 + r) * LDA2 + k];
                #pragma unroll
                for (int c = 0; c < 4; c++) {
                    u64 d = addf32x2(a2, b2[c]);
                    d &= 0x7FFFFFFF7FFFFFFFull;
                    acc[r][c] = addf32x2(acc[r][c], d);
                }
            }
        }
        __syncthreads();
    }

    #pragma unroll
    for (int r = 0; r < 8; r++) {
        int row = bi * 128 + ty * 8 + r;
        size_t base = (size_t)row * B + bj * 128 + tx * 8;
        float wv[8];
        #pragma unroll
        for (int c = 0; c < 4; c++) { wv[2*c] = lo32f(acc[r][c]); wv[2*c+1] = hi32f(acc[r][c]); }
        #pragma unroll
        for (int q = 0; q < 2; q++) {
            float4 w4 = make_float4(wv[q*4+0], wv[q*4+1], wv[q*4+2], wv[q*4+3]);
            ((float4*)(g_W + base))[q] = w4;
            float4 k4 = make_float4(__expf(-EPS_INV * w4.x), __expf(-EPS_INV * w4.y),
                                    __expf(-EPS_INV * w4.z), __expf(-EPS_INV * w4.w));
            ((float4*)(g_K + base))[q] = k4;
        }
    }
}

// ---------------- persistent Sinkhorn + per-row loss -------------------------
// 128 blocks x 256 threads, all co-resident. Block b owns rows/cols
// [16b, 16b+16). K rows (128KB/block) become L1-resident after iter 0.
__device__ __forceinline__ void grid_barrier(int slot) {
    __threadfence();
    __syncthreads();
    if (threadIdx.x == 0) {
        atomicAdd(&g_bar[slot], 1);
        while (*((volatile int*)&g_bar[slot]) < PBLK) __nanosleep(32);
        __threadfence();
    }
    __syncthreads();
}

__global__ __launch_bounds__(256) void sinkhorn_kernel() {
    __shared__ float bsm[B];        // 8KB: full b vector
    __shared__ float avec[RPB];     // owned a values
    __shared__ float red[256];      // phase-C reduction scratch

    int tid = threadIdx.x, w = tid >> 5, lane = tid & 31;
    int blk = blockIdx.x;

    #pragma unroll
    for (int q = 0; q < B / 256; q++) bsm[tid + q * 256] = 1.0f;
    __syncthreads();

    int bar = 0;
    for (int it = 0; it < N_ITERS; it++) {
        // Phase A: a_i = 1 / (K_i . b) for owned rows (warp per row, x2)
        #pragma unroll
        for (int rr = 0; rr < 2; rr++) {
            int row = blk * RPB + w * 2 + rr;
            const float4* Kr = (const float4*)(g_K + (size_t)row * B);
            const float4* bv = (const float4*)bsm;
            float s = 0.0f;
            #pragma unroll
            for (int q = 0; q < 16; q++) {
                float4 k = Kr[q * 32 + lane];
                float4 v = bv[q * 32 + lane];
                s += k.x * v.x + k.y * v.y + k.z * v.z + k.w * v.w;
            }
            #pragma unroll
            for (int o = 16; o > 0; o >>= 1) s += __shfl_down_sync(0xffffffffu, s, o);
            if (lane == 0) avec[w * 2 + rr] = __fdividef(1.0f, s);
        }
        __syncthreads();

        // Phase B: partial column sums over owned rows; thread owns 8 cols
        {
            float4 p0 = make_float4(0.f, 0.f, 0.f, 0.f);
            float4 p1 = make_float4(0.f, 0.f, 0.f, 0.f);
            #pragma unroll
            for (int i = 0; i < RPB; i++) {
                const float4* Kr = (const float4*)(g_K + (size_t)(blk * RPB + i) * B) + tid * 2;
                float ai = avec[i];
                float4 k0 = Kr[0], k1 = Kr[1];
                p0.x += k0.x * ai; p0.y += k0.y * ai; p0.z += k0.z * ai; p0.w += k0.w * ai;
                p1.x += k1.x * ai; p1.y += k1.y * ai; p1.z += k1.z * ai; p1.w += k1.w * ai;
            }
            float4* pp = (float4*)(g_part + (size_t)blk * B) + tid * 2;
            pp[0] = p0; pp[1] = p1;
        }
        grid_barrier(bar++);

        // Phase C: b_j = 1 / sum_p part[p][j] for owned cols (16 cols x 16 groups)
        {
            int c  = tid & 15;
            int pg = tid >> 4;
            int j  = blk * RPB + c;
            float s = 0.0f;
            #pragma unroll
            for (int p = 0; p < 8; p++)
                s += g_part[(size_t)(pg * 8 + p) * B + j];
            red[pg * 16 + c] = s;
            __syncthreads();
            #pragma unroll
            for (int off = 8; off > 0; off >>= 1) {
                if (pg < off) red[pg * 16 + c] += red[(pg + off) * 16 + c];
                __syncthreads();
            }
            if (pg == 0) g_b[j] = __fdividef(1.0f, red[c]);
        }
        grid_barrier(bar++);

        // reload full b
        #pragma unroll
        for (int q = 0; q < B / 256; q++) bsm[tid + q * 256] = g_b[tid + q * 256];
        __syncthreads();
    }

    // Loss: lp[row] = a_row * sum_j K*W*b  (warp per row, x2)
    #pragma unroll
    for (int rr = 0; rr < 2; rr++) {
        int row = blk * RPB + w * 2 + rr;
        const float4* Kr = (const float4*)(g_K + (size_t)row * B);
        const float4* Wr = (const float4*)(g_W + (size_t)row * B);
        const float4* bv = (const float4*)bsm;
        float s = 0.0f;
        #pragma unroll
        for (int q = 0; q < 16; q++) {
            float4 k = Kr[q * 32 + lane];
            float4 wv = Wr[q * 32 + lane];
            float4 v = bv[q * 32 + lane];
            s += k.x * wv.x * v.x + k.y * wv.y * v.y + k.z * wv.z * v.z + k.w * wv.w * v.w;
        }
        #pragma unroll
        for (int o = 16; o > 0; o >>= 1) s += __shfl_down_sync(0xffffffffu, s, o);
        if (lane == 0) g_lp[row] = avec[w * 2 + rr] * s;
    }
}

__global__ __launch_bounds__(256) void loss_final_kernel(float* __restrict__ out) {
    __shared__ float sm[8];
    int tid = threadIdx.x;
    float s = 0.0f;
    #pragma unroll
    for (int l = 0; l < 8; l++) s += g_lp[tid + l * 256];
    #pragma unroll
    for (int o = 16; o > 0; o >>= 1) s += __shfl_down_sync(0xffffffffu, s, o);
    int lane = tid & 31, w = tid >> 5;
    if (lane == 0) sm[w] = s;
    __syncthreads();
    if (w == 0) {
        s = (lane < 8) ? sm[lane] : 0.0f;
        #pragma unroll
        for (int o = 4; o > 0; o >>= 1) s += __shfl_down_sync(0xffu, s, o);
        if (lane == 0) out[0] = LOSS_SCALE * s;
    }
}

// ---------------- launcher ---------------------------------------------------
extern "C" void kernel_launch(void* const* d_in, const int* in_sizes, int n_in,
                              void* d_out, int out_size) {
    const float* ys = (const float*)d_in[0];
    const float* yt = (const float*)d_in[1];
    float* out = (float*)d_out;

    softmax_kernel<<<2 * B, 256>>>(ys, yt);
    zero_bar_kernel<<<1, 64>>>();
    cdist_kernel<<<dim3(16, 16), 256>>>();
    sinkhorn_kernel<<<PBLK, 256>>>();
    loss_final_kernel<<<1, 256>>>(out);
}

// round 8
// speedup vs baseline: 1.0262x; 1.0262x over previous
#include <cuda_runtime.h>
#include <cuda_bf16.h>

#define B 2048
#define C 1024
#define TEMP_INV 0.5f
#define EPS_INV 10.0f
#define N_ITERS 20
#define LOSS_SCALE 0.001f
#define PBLK 128            // persistent blocks, all co-resident (< 148 SMs)
#define RPB (B / PBLK)      // 16 rows/cols owned per block
#define STHR 512            // sinkhorn threads per block

typedef unsigned long long u64;
typedef unsigned int u32;

// ---------------- scratch (device globals; no runtime allocation) -----------
__device__ float g_ps[B * C];
__device__ float g_pt[B * C];
__device__ float g_W [B * B];
__device__ float g_K [B * B];
__device__ float g_b [B];
__device__ float g_lp[B];
__device__ float g_part[PBLK * B];   // per-block partial column sums
__device__ int   g_bar[64];          // one counter per barrier instance

// ---------------- f32x2 helpers ---------------------------------------------
__device__ __forceinline__ u64 addf32x2(u64 a, u64 b) {
    u64 r;
    asm("add.rn.f32x2 %0, %1, %2;" : "=l"(r) : "l"(a), "l"(b));
    return r;
}
__device__ __forceinline__ u64 dupf(float f) {
    u32 u = __float_as_uint(f);
    return (u64)u | ((u64)u << 32);
}
__device__ __forceinline__ float lo32f(u64 v) { return __uint_as_float((u32)v); }
__device__ __forceinline__ float hi32f(u64 v) { return __uint_as_float((u32)(v >> 32)); }

// ---------------- softmax: one block per row (4096 rows) --------------------
__global__ __launch_bounds__(256) void softmax_kernel(const float* __restrict__ ys,
                                                      const float* __restrict__ yt) {
    int row = blockIdx.x;
    const float* src = (row < B) ? (ys + (size_t)row * C) : (yt + (size_t)(row - B) * C);
    float*       dst = (row < B) ? (g_ps + (size_t)row * C) : (g_pt + (size_t)(row - B) * C);
    int tid = threadIdx.x;

    float4 x = ((const float4*)src)[tid];
    x.x *= TEMP_INV; x.y *= TEMP_INV; x.z *= TEMP_INV; x.w *= TEMP_INV;

    __shared__ float smx[8];
    __shared__ float bc;

    float m = fmaxf(fmaxf(x.x, x.y), fmaxf(x.z, x.w));
    #pragma unroll
    for (int o = 16; o > 0; o >>= 1) m = fmaxf(m, __shfl_down_sync(0xffffffffu, m, o));
    int lane = tid & 31, w = tid >> 5;
    if (lane == 0) smx[w] = m;
    __syncthreads();
    if (w == 0) {
        m = (lane < 8) ? smx[lane] : -1e30f;
        #pragma unroll
        for (int o = 4; o > 0; o >>= 1) m = fmaxf(m, __shfl_down_sync(0xffu, m, o));
        if (lane == 0) bc = m;
    }
    __syncthreads();
    m = bc;

    float4 e;
    e.x = __expf(x.x - m); e.y = __expf(x.y - m);
    e.z = __expf(x.z - m); e.w = __expf(x.w - m);
    float s = (e.x + e.y) + (e.z + e.w);

    #pragma unroll
    for (int o = 16; o > 0; o >>= 1) s += __shfl_down_sync(0xffffffffu, s, o);
    __syncthreads();
    if (lane == 0) smx[w] = s;
    __syncthreads();
    if (w == 0) {
        s = (lane < 8) ? smx[lane] : 0.0f;
        #pragma unroll
        for (int o = 4; o > 0; o >>= 1) s += __shfl_down_sync(0xffu, s, o);
        if (lane == 0) bc = s;
    }
    __syncthreads();
    float inv = __fdividef(1.0f, bc);

    e.x *= inv; e.y *= inv; e.z *= inv; e.w *= inv;
    ((float4*)dst)[tid] = e;
}

__global__ void zero_bar_kernel() {
    if (threadIdx.x < 64) g_bar[threadIdx.x] = 0;
}

// ---------------- cdist L1 (f32x2 packed) + K --------------------------------
#define KC   32
#define LDA2 33
#define LDBT 130

__global__ __launch_bounds__(256, 2) void cdist_kernel() {
    __shared__ u64   As2[128 * LDA2];
    __shared__ float BsT[KC * LDBT];

    int bi = blockIdx.y, bj = blockIdx.x;
    int tid = threadIdx.x;
    int tx = tid & 15, ty = tid >> 4;

    const float* Abase = g_ps + (size_t)(bi * 128) * C;
    const float* Bbase = g_pt + (size_t)(bj * 128) * C;

    u64 acc[8][4];
    #pragma unroll
    for (int r = 0; r < 8; r++)
        #pragma unroll
        for (int c = 0; c < 4; c++) acc[r][c] = 0ull;

    for (int k0 = 0; k0 < C; k0 += KC) {
        #pragma unroll
        for (int l = 0; l < 4; l++) {
            int v   = tid + l * 256;
            int row = v >> 3;
            int kq  = (v & 7) << 2;
            float4 a4 = *(const float4*)(Abase + (size_t)row * C + k0 + kq);
            As2[row * LDA2 + kq + 0] = dupf(a4.x);
            As2[row * LDA2 + kq + 1] = dupf(a4.y);
            As2[row * LDA2 + kq + 2] = dupf(a4.z);
            As2[row * LDA2 + kq + 3] = dupf(a4.w);
            float4 b4 = *(const float4*)(Bbase + (size_t)row * C + k0 + kq);
            BsT[(kq + 0) * LDBT + row] = -b4.x;
            BsT[(kq + 1) * LDBT + row] = -b4.y;
            BsT[(kq + 2) * LDBT + row] = -b4.z;
            BsT[(kq + 3) * LDBT + row] = -b4.w;
        }
        __syncthreads();

        #pragma unroll 4
        for (int k = 0; k < KC; k++) {
            u64 b2[4];
            const u64* bp = (const u64*)(BsT + k * LDBT + tx * 8);
            #pragma unroll
            for (int c = 0; c < 4; c++) b2[c] = bp[c];
            #pragma unroll
            for (int r = 0; r < 8; r++) {
                u64 a2 = As2[(ty * 8 + r) * LDA2 + k];
                #pragma unroll
                for (int c = 0; c < 4; c++) {
                    u64 d = addf32x2(a2, b2[c]);
                    d &= 0x7FFFFFFF7FFFFFFFull;
                    acc[r][c] = addf32x2(acc[r][c], d);
                }
            }
        }
        __syncthreads();
    }

    #pragma unroll
    for (int r = 0; r < 8; r++) {
        int row = bi * 128 + ty * 8 + r;
        size_t base = (size_t)row * B + bj * 128 + tx * 8;
        float wv[8];
        #pragma unroll
        for (int c = 0; c < 4; c++) { wv[2*c] = lo32f(acc[r][c]); wv[2*c+1] = hi32f(acc[r][c]); }
        #pragma unroll
        for (int q = 0; q < 2; q++) {
            float4 w4 = make_float4(wv[q*4+0], wv[q*4+1], wv[q*4+2], wv[q*4+3]);
            ((float4*)(g_W + base))[q] = w4;
            float4 k4 = make_float4(__expf(-EPS_INV * w4.x), __expf(-EPS_INV * w4.y),
                                    __expf(-EPS_INV * w4.z), __expf(-EPS_INV * w4.w));
            ((float4*)(g_K + base))[q] = k4;
        }
    }
}

// ---------------- persistent Sinkhorn (SMEM-resident K rows) + loss ----------
__device__ __forceinline__ void grid_barrier(int slot) {
    __syncthreads();
    if (threadIdx.x == 0) {
        __threadfence();
        atomicAdd(&g_bar[slot], 1);
        while (*((volatile int*)&g_bar[slot]) < PBLK) { }
        __threadfence();
    }
    __syncthreads();
}

__global__ __launch_bounds__(STHR) void sinkhorn_kernel() {
    extern __shared__ float smem[];
    float* Ks   = smem;                 // [RPB][B] owned K rows, 128 KB
    float* bsm  = smem + RPB * B;       // [B]
    float* avec = bsm + B;              // [RPB] (padded to 32)
    float* red  = avec + 32;            // [STHR]

    int tid = threadIdx.x, w = tid >> 5, lane = tid & 31;
    int blk = blockIdx.x;

    // preload owned K rows into SMEM (once), init b = 1
    {
        const float4* src = (const float4*)(g_K + (size_t)(blk * RPB) * B);
        float4* dst = (float4*)Ks;
        #pragma unroll
        for (int q = 0; q < (RPB * B / 4) / STHR; q++)
            dst[tid + q * STHR] = src[tid + q * STHR];
        #pragma unroll
        for (int q = 0; q < B / STHR; q++) bsm[tid + q * STHR] = 1.0f;
    }
    __syncthreads();

    int bar = 0;
    for (int it = 0; it < N_ITERS; it++) {
        // Phase A: a_i = 1/(K_i . b), warp per owned row (16 warps = 16 rows)
        {
            const float4* Kr = (const float4*)(Ks + (size_t)w * B);
            const float4* bv = (const float4*)bsm;
            float s = 0.0f;
            #pragma unroll
            for (int q = 0; q < 16; q++) {
                float4 k = Kr[q * 32 + lane];
                float4 v = bv[q * 32 + lane];
                s += k.x * v.x + k.y * v.y + k.z * v.z + k.w * v.w;
            }
            #pragma unroll
            for (int o = 16; o > 0; o >>= 1) s += __shfl_down_sync(0xffffffffu, s, o);
            if (lane == 0) avec[w] = __fdividef(1.0f, s);
        }
        __syncthreads();

        // Phase B: partial column sums over owned rows; thread owns 4 cols
        {
            float4 acc = make_float4(0.f, 0.f, 0.f, 0.f);
            #pragma unroll
            for (int i = 0; i < RPB; i++) {
                float4 k = ((const float4*)(Ks + (size_t)i * B))[tid];
                float ai = avec[i];
                acc.x += k.x * ai; acc.y += k.y * ai; acc.z += k.z * ai; acc.w += k.w * ai;
            }
            ((float4*)(g_part + (size_t)blk * B))[tid] = acc;
        }
        grid_barrier(bar++);

        // Phase C: b_j = 1/sum_p part[p][j] for owned 16 cols; 32 groups of 4
        {
            int c  = tid & 15;
            int pg = tid >> 4;       // 0..31
            int j  = blk * RPB + c;
            float s = 0.0f;
            #pragma unroll
            for (int p = 0; p < 4; p++)
                s += g_part[(size_t)(pg * 4 + p) * B + j];
            red[pg * 16 + c] = s;
            __syncthreads();
            #pragma unroll
            for (int off = 16; off > 0; off >>= 1) {
                if (pg < off) red[pg * 16 + c] += red[(pg + off) * 16 + c];
                __syncthreads();
            }
            if (pg == 0) g_b[j] = __fdividef(1.0f, red[c]);
        }
        grid_barrier(bar++);

        // reload full b into SMEM
        #pragma unroll
        for (int q = 0; q < B / STHR; q++) bsm[tid + q * STHR] = g_b[tid + q * STHR];
        __syncthreads();
    }

    // Loss: lp[row] = a_row * sum_j Ks*W*b, warp per owned row
    {
        int row = blk * RPB + w;
        const float4* Kr = (const float4*)(Ks + (size_t)w * B);
        const float4* Wr = (const float4*)(g_W + (size_t)row * B);
        const float4* bv = (const float4*)bsm;
        float s = 0.0f;
        #pragma unroll
        for (int q = 0; q < 16; q++) {
            float4 k  = Kr[q * 32 + lane];
            float4 wv = Wr[q * 32 + lane];
            float4 v  = bv[q * 32 + lane];
            s += k.x * wv.x * v.x + k.y * wv.y * v.y + k.z * wv.z * v.z + k.w * wv.w * v.w;
        }
        #pragma unroll
        for (int o = 16; o > 0; o >>= 1) s += __shfl_down_sync(0xffffffffu, s, o);
        if (lane == 0) g_lp[row] = avec[w] * s;
    }
}

__global__ __launch_bounds__(256) void loss_final_kernel(float* __restrict__ out) {
    __shared__ float sm[8];
    int tid = threadIdx.x;
    float s = 0.0f;
    #pragma unroll
    for (int l = 0; l < 8; l++) s += g_lp[tid + l * 256];
    #pragma unroll
    for (int o = 16; o > 0; o >>= 1) s += __shfl_down_sync(0xffffffffu, s, o);
    int lane = tid & 31, w = tid >> 5;
    if (lane == 0) sm[w] = s;
    __syncthreads();
    if (w == 0) {
        s = (lane < 8) ? sm[lane] : 0.0f;
        #pragma unroll
        for (int o = 4; o > 0; o >>= 1) s += __shfl_down_sync(0xffu, s, o);
        if (lane == 0) out[0] = LOSS_SCALE * s;
    }
}

// ---------------- launcher ---------------------------------------------------
#define SINK_SMEM ((RPB * B + B + 32 + STHR) * (int)sizeof(float))

extern "C" void kernel_launch(void* const* d_in, const int* in_sizes, int n_in,
                              void* d_out, int out_size) {
    const float* ys = (const float*)d_in[0];
    const float* yt = (const float*)d_in[1];
    float* out = (float*)d_out;

    static int smem_set = 0;
    if (!smem_set) {
        cudaFuncSetAttribute(sinkhorn_kernel,
                             cudaFuncAttributeMaxDynamicSharedMemorySize, SINK_SMEM);
        smem_set = 1;
    }

    softmax_kernel<<<2 * B, 256>>>(ys, yt);
    zero_bar_kernel<<<1, 64>>>();
    cdist_kernel<<<dim3(16, 16), 256>>>();
    sinkhorn_kernel<<<PBLK, STHR, SINK_SMEM>>>();
    loss_final_kernel<<<1, 256>>>(out);
}

// round 10
// speedup vs baseline: 1.2601x; 1.2278x over previous
#include <cuda_runtime.h>
#include <cuda_bf16.h>

#define B 2048
#define C 1024
#define TEMP_INV 0.5f
#define EPS_INV 10.0f
#define N_ITERS 20
#define LOSS_SCALE 0.001f
#define PBLK 128            // persistent blocks, all co-resident (< 148 SMs)
#define RPB (B / PBLK)      // 16 rows/cols owned per block
#define STHR 512            // sinkhorn threads per block

typedef unsigned long long u64;
typedef unsigned int u32;

// ---------------- scratch (device globals; no runtime allocation) -----------
__device__ float g_ps[B * C];
__device__ float g_pt[B * C];
__device__ float g_W [B * B];
__device__ float g_K [B * B];
__device__ float g_b [B];
__device__ float g_lp[B];
__device__ float g_part[PBLK * B];   // per-block partial column sums
__device__ int   g_bar[64];          // one counter per barrier instance

// ---------------- softmax: one block per row (4096 rows) --------------------
__global__ __launch_bounds__(256) void softmax_kernel(const float* __restrict__ ys,
                                                      const float* __restrict__ yt) {
    int row = blockIdx.x;
    const float* src = (row < B) ? (ys + (size_t)row * C) : (yt + (size_t)(row - B) * C);
    float*       dst = (row < B) ? (g_ps + (size_t)row * C) : (g_pt + (size_t)(row - B) * C);
    int tid = threadIdx.x;

    float4 x = ((const float4*)src)[tid];
    x.x *= TEMP_INV; x.y *= TEMP_INV; x.z *= TEMP_INV; x.w *= TEMP_INV;

    __shared__ float smx[8];
    __shared__ float bc;

    float m = fmaxf(fmaxf(x.x, x.y), fmaxf(x.z, x.w));
    #pragma unroll
    for (int o = 16; o > 0; o >>= 1) m = fmaxf(m, __shfl_down_sync(0xffffffffu, m, o));
    int lane = tid & 31, w = tid >> 5;
    if (lane == 0) smx[w] = m;
    __syncthreads();
    if (w == 0) {
        m = (lane < 8) ? smx[lane] : -1e30f;
        #pragma unroll
        for (int o = 4; o > 0; o >>= 1) m = fmaxf(m, __shfl_down_sync(0xffu, m, o));
        if (lane == 0) bc = m;
    }
    __syncthreads();
    m = bc;

    float4 e;
    e.x = __expf(x.x - m); e.y = __expf(x.y - m);
    e.z = __expf(x.z - m); e.w = __expf(x.w - m);
    float s = (e.x + e.y) + (e.z + e.w);

    #pragma unroll
    for (int o = 16; o > 0; o >>= 1) s += __shfl_down_sync(0xffffffffu, s, o);
    __syncthreads();
    if (lane == 0) smx[w] = s;
    __syncthreads();
    if (w == 0) {
        s = (lane < 8) ? smx[lane] : 0.0f;
        #pragma unroll
        for (int o = 4; o > 0; o >>= 1) s += __shfl_down_sync(0xffu, s, o);
        if (lane == 0) bc = s;
    }
    __syncthreads();
    float inv = __fdividef(1.0f, bc);

    e.x *= inv; e.y *= inv; e.z *= inv; e.w *= inv;
    ((float4*)dst)[tid] = e;
}

__global__ void zero_bar_kernel() {
    if (threadIdx.x < 64) g_bar[threadIdx.x] = 0;
}

// ---------------- cdist via min-identity: W = 2 - 2*sum_k min(p,q) ----------
// Tile 128x128, 256 threads (tx 0..15, ty 0..15), 8x8 per thread.
// Cols assigned strided: j = tx + 16c  -> conflict-free LDS on B.
// A row-major (broadcast reads), B k-major. Register-prefetched LDG.
#define KC2 16
#define LDA 20     // As[128][20] floats (float4-aligned pad)
#define LDB 132    // Bs[16][132] floats

__global__ __launch_bounds__(256, 2) void cdist_kernel() {
    __shared__ float As[128 * LDA];
    __shared__ float Bs[KC2 * LDB];

    int bi = blockIdx.y, bj = blockIdx.x;
    int tid = threadIdx.x;
    int tx = tid & 15, ty = tid >> 4;

    const float* Ab = g_ps + (size_t)(bi * 128) * C;
    const float* Bb = g_pt + (size_t)(bj * 128) * C;

    float acc[8][8];
    #pragma unroll
    for (int r = 0; r < 8; r++)
        #pragma unroll
        for (int c = 0; c < 8; c++) acc[r][c] = 0.0f;

    // prefetch chunk 0 into registers (2 float4 per matrix per thread)
    float4 pa[2], pb[2];
    #pragma unroll
    for (int l = 0; l < 2; l++) {
        int idx = tid + l * 256;            // 0..511
        int row = idx >> 2, q = idx & 3;    // row 0..127, q 0..3
        pa[l] = *(const float4*)(Ab + (size_t)row * C + 4 * q);
        pb[l] = *(const float4*)(Bb + (size_t)row * C + 4 * q);
    }

    for (int k0 = 0; k0 < C; k0 += KC2) {
        __syncthreads();   // previous chunk's compute done
        #pragma unroll
        for (int l = 0; l < 2; l++) {
            int idx = tid + l * 256;
            int row = idx >> 2, q = idx & 3;
            *(float4*)&As[row * LDA + 4 * q] = pa[l];     // A row-major
            float4 b4 = pb[l];                             // B k-major (transpose)
            Bs[(4 * q + 0) * LDB + row] = b4.x;
            Bs[(4 * q + 1) * LDB + row] = b4.y;
            Bs[(4 * q + 2) * LDB + row] = b4.z;
            Bs[(4 * q + 3) * LDB + row] = b4.w;
        }
        __syncthreads();

        if (k0 + KC2 < C) {   // issue next chunk's loads early (hidden by compute)
            #pragma unroll
            for (int l = 0; l < 2; l++) {
                int idx = tid + l * 256;
                int row = idx >> 2, q = idx & 3;
                pa[l] = *(const float4*)(Ab + (size_t)row * C + k0 + KC2 + 4 * q);
                pb[l] = *(const float4*)(Bb + (size_t)row * C + k0 + KC2 + 4 * q);
            }
        }

        #pragma unroll
        for (int k = 0; k < KC2; k++) {
            float a[8], b[8];
            #pragma unroll
            for (int r = 0; r < 8; r++) a[r] = As[(ty * 8 + r) * LDA + k];
            #pragma unroll
            for (int c = 0; c < 8; c++) b[c] = Bs[k * LDB + tx + 16 * c];
            #pragma unroll
            for (int r = 0; r < 8; r++)
                #pragma unroll
                for (int c = 0; c < 8; c++)
                    acc[r][c] += fminf(a[r], b[c]);   // FMNMX(alu) + FADD(fma)
        }
    }

    // epilogue: W = 2 - 2S, K = exp(-10W)
    #pragma unroll
    for (int r = 0; r < 8; r++) {
        int row = bi * 128 + ty * 8 + r;
        size_t base = (size_t)row * B + bj * 128;
        #pragma unroll
        for (int c = 0; c < 8; c++) {
            int col = tx + 16 * c;
            float wv = 2.0f - 2.0f * acc[r][c];
            g_W[base + col] = wv;
            g_K[base + col] = __expf(-EPS_INV * wv);
        }
    }
}

// ---------------- persistent Sinkhorn (SMEM-resident K rows) + loss ----------
__device__ __forceinline__ void grid_barrier(int slot) {
    __syncthreads();
    if (threadIdx.x == 0) {
        __threadfence();
        atomicAdd(&g_bar[slot], 1);
        while (*((volatile int*)&g_bar[slot]) < PBLK) { }
        __threadfence();
    }
    __syncthreads();
}

__global__ __launch_bounds__(STHR) void sinkhorn_kernel() {
    extern __shared__ float smem[];
    float* Ks   = smem;                 // [RPB][B] owned K rows, 128 KB
    float* bsm  = smem + RPB * B;       // [B]
    float* avec = bsm + B;              // [RPB] (padded to 32)
    float* red  = avec + 32;            // [STHR]

    int tid = threadIdx.x, w = tid >> 5, lane = tid & 31;
    int blk = blockIdx.x;

    {
        const float4* src = (const float4*)(g_K + (size_t)(blk * RPB) * B);
        float4* dst = (float4*)Ks;
        #pragma unroll
        for (int q = 0; q < (RPB * B / 4) / STHR; q++)
            dst[tid + q * STHR] = src[tid + q * STHR];
        #pragma unroll
        for (int q = 0; q < B / STHR; q++) bsm[tid + q * STHR] = 1.0f;
    }
    __syncthreads();

    int bar = 0;
    for (int it = 0; it < N_ITERS; it++) {
        // Phase A: a_i = 1/(K_i . b), warp per owned row
        {
            const float4* Kr = (const float4*)(Ks + (size_t)w * B);
            const float4* bv = (const float4*)bsm;
            float s = 0.0f;
            #pragma unroll
            for (int q = 0; q < 16; q++) {
                float4 k = Kr[q * 32 + lane];
                float4 v = bv[q * 32 + lane];
                s += k.x * v.x + k.y * v.y + k.z * v.z + k.w * v.w;
            }
            #pragma unroll
            for (int o = 16; o > 0; o >>= 1) s += __shfl_down_sync(0xffffffffu, s, o);
            if (lane == 0) avec[w] = __fdividef(1.0f, s);
        }
        __syncthreads();

        // Phase B: partial column sums over owned rows
        {
            float4 acc = make_float4(0.f, 0.f, 0.f, 0.f);
            #pragma unroll
            for (int i = 0; i < RPB; i++) {
                float4 k = ((const float4*)(Ks + (size_t)i * B))[tid];
                float ai = avec[i];
                acc.x += k.x * ai; acc.y += k.y * ai; acc.z += k.z * ai; acc.w += k.w * ai;
            }
            ((float4*)(g_part + (size_t)blk * B))[tid] = acc;
        }
        grid_barrier(bar++);

        // Phase C: b_j = 1/sum_p part[p][j] for owned 16 cols
        {
            int c  = tid & 15;
            int pg = tid >> 4;
            int j  = blk * RPB + c;
            float s = 0.0f;
            #pragma unroll
            for (int p = 0; p < 4; p++)
                s += g_part[(size_t)(pg * 4 + p) * B + j];
            red[pg * 16 + c] = s;
            __syncthreads();
            #pragma unroll
            for (int off = 16; off > 0; off >>= 1) {
                if (pg < off) red[pg * 16 + c] += red[(pg + off) * 16 + c];
                __syncthreads();
            }
            if (pg == 0) g_b[j] = __fdividef(1.0f, red[c]);
        }
        grid_barrier(bar++);

        #pragma unroll
        for (int q = 0; q < B / STHR; q++) bsm[tid + q * STHR] = g_b[tid + q * STHR];
        __syncthreads();
    }

    // Loss: lp[row] = a_row * sum_j Ks*W*b, warp per owned row
    {
        int row = blk * RPB + w;
        const float4* Kr = (const float4*)(Ks + (size_t)w * B);
        const float4* Wr = (const float4*)(g_W + (size_t)row * B);
        const float4* bv = (const float4*)bsm;
        float s = 0.0f;
        #pragma unroll
        for (int q = 0; q < 16; q++) {
            float4 k  = Kr[q * 32 + lane];
            float4 wv = Wr[q * 32 + lane];
            float4 v  = bv[q * 32 + lane];
            s += k.x * wv.x * v.x + k.y * wv.y * v.y + k.z * wv.z * v.z + k.w * wv.w * v.w;
        }
        #pragma unroll
        for (int o = 16; o > 0; o >>= 1) s += __shfl_down_sync(0xffffffffu, s, o);
        if (lane == 0) g_lp[row] = avec[w] * s;
    }
}

__global__ __launch_bounds__(256) void loss_final_kernel(float* __restrict__ out) {
    __shared__ float sm[8];
    int tid = threadIdx.x;
    float s = 0.0f;
    #pragma unroll
    for (int l = 0; l < 8; l++) s += g_lp[tid + l * 256];
    #pragma unroll
    for (int o = 16; o > 0; o >>= 1) s += __shfl_down_sync(0xffffffffu, s, o);
    int lane = tid & 31, w = tid >> 5;
    if (lane == 0) sm[w] = s;
    __syncthreads();
    if (w == 0) {
        s = (lane < 8) ? sm[lane] : 0.0f;
        #pragma unroll
        for (int o = 4; o > 0; o >>= 1) s += __shfl_down_sync(0xffu, s, o);
        if (lane == 0) out[0] = LOSS_SCALE * s;
    }
}

// ---------------- launcher ---------------------------------------------------
#define SINK_SMEM ((RPB * B + B + 32 + STHR) * (int)sizeof(float))

extern "C" void kernel_launch(void* const* d_in, const int* in_sizes, int n_in,
                              void* d_out, int out_size) {
    const float* ys = (const float*)d_in[0];
    const float* yt = (const float*)d_in[1];
    float* out = (float*)d_out;

    static int smem_set = 0;
    if (!smem_set) {
        cudaFuncSetAttribute(sinkhorn_kernel,
                             cudaFuncAttributeMaxDynamicSharedMemorySize, SINK_SMEM);
        smem_set = 1;
    }

    softmax_kernel<<<2 * B, 256>>>(ys, yt);
    zero_bar_kernel<<<1, 64>>>();
    cdist_kernel<<<dim3(16, 16), 256>>>();
    sinkhorn_kernel<<<PBLK, STHR, SINK_SMEM>>>();
    loss_final_kernel<<<1, 256>>>(out);
}

// round 11
// speedup vs baseline: 1.6888x; 1.3402x over previous
#include <cuda_runtime.h>
#include <cuda_fp16.h>

#define B 2048
#define C 1024
#define TEMP_INV 0.5f
#define EPS_INV 10.0f
#define N_ITERS 20
#define LOSS_SCALE 0.001f
#define PBLK 128            // persistent blocks, all co-resident (< 148 SMs)
#define RPB (B / PBLK)      // 16 rows/cols owned per block
#define STHR 512            // sinkhorn threads per block

typedef unsigned int u32;

// ---------------- scratch (device globals; no runtime allocation) -----------
__device__ __half g_psh[B * C];      // softmax(y_s/2) in fp16
__device__ __half g_pth[B * C];      // softmax(y_t/2) in fp16
__device__ float g_W [B * B];
__device__ float g_K [B * B];
__device__ float g_b [B];
__device__ float g_lp[B];
__device__ float g_part[PBLK * B];   // per-block partial column sums
__device__ int   g_bar[64];          // one counter per barrier instance

// ---------------- softmax: one block per row (4096 rows), fp16 out ----------
__global__ __launch_bounds__(256) void softmax_kernel(const float* __restrict__ ys,
                                                      const float* __restrict__ yt) {
    int row = blockIdx.x;
    const float* src = (row < B) ? (ys + (size_t)row * C) : (yt + (size_t)(row - B) * C);
    __half*      dst = (row < B) ? (g_psh + (size_t)row * C) : (g_pth + (size_t)(row - B) * C);
    int tid = threadIdx.x;

    float4 x = ((const float4*)src)[tid];
    x.x *= TEMP_INV; x.y *= TEMP_INV; x.z *= TEMP_INV; x.w *= TEMP_INV;

    __shared__ float smx[8];
    __shared__ float bc;

    float m = fmaxf(fmaxf(x.x, x.y), fmaxf(x.z, x.w));
    #pragma unroll
    for (int o = 16; o > 0; o >>= 1) m = fmaxf(m, __shfl_down_sync(0xffffffffu, m, o));
    int lane = tid & 31, w = tid >> 5;
    if (lane == 0) smx[w] = m;
    __syncthreads();
    if (w == 0) {
        m = (lane < 8) ? smx[lane] : -1e30f;
        #pragma unroll
        for (int o = 4; o > 0; o >>= 1) m = fmaxf(m, __shfl_down_sync(0xffu, m, o));
        if (lane == 0) bc = m;
    }
    __syncthreads();
    m = bc;

    float4 e;
    e.x = __expf(x.x - m); e.y = __expf(x.y - m);
    e.z = __expf(x.z - m); e.w = __expf(x.w - m);
    float s = (e.x + e.y) + (e.z + e.w);

    #pragma unroll
    for (int o = 16; o > 0; o >>= 1) s += __shfl_down_sync(0xffffffffu, s, o);
    __syncthreads();
    if (lane == 0) smx[w] = s;
    __syncthreads();
    if (w == 0) {
        s = (lane < 8) ? smx[lane] : 0.0f;
        #pragma unroll
        for (int o = 4; o > 0; o >>= 1) s += __shfl_down_sync(0xffu, s, o);
        if (lane == 0) bc = s;
    }
    __syncthreads();
    float inv = __fdividef(1.0f, bc);

    __half2 h0 = __floats2half2_rn(e.x * inv, e.y * inv);
    __half2 h1 = __floats2half2_rn(e.z * inv, e.w * inv);
    ((__half2*)dst)[2 * tid]     = h0;
    ((__half2*)dst)[2 * tid + 1] = h1;
}

__global__ void zero_bar_kernel() {
    if (threadIdx.x < 64) g_bar[threadIdx.x] = 0;
}

// ---------------- cdist via min-identity, fp16 packed ------------------------
// W = 2 - 2*sum_k min(p,q); k packed 2-wide in half2 (HMNMX2 + HADD2).
// Tile 128x128; 512 threads (tx 0..15 col-group, ty 0..31 row-group);
// 4x8 outputs per thread. A smem [row][kk], B smem [col][kk], stride 18 half2.
#define LDH 18

__global__ __launch_bounds__(512) void cdist_kernel() {
    __shared__ __half2 As[128 * LDH];
    __shared__ __half2 Bs[128 * LDH];

    int tid = threadIdx.x;
    int tx = tid & 15, ty = tid >> 4;        // col-group, row-group
    int lrow = tid >> 2, lq = tid & 3;       // loader: row 0..127, quarter 0..3

    #pragma unroll 1
    for (int s = 0; s < 2; s++) {
        int t  = blockIdx.x * 2 + s;
        int bi = t >> 4, bj = t & 15;
        const __half* Ab = g_psh + (size_t)(bi * 128) * C;
        const __half* Bb = g_pth + (size_t)(bj * 128) * C;

        float facc[4][8];
        #pragma unroll
        for (int r = 0; r < 4; r++)
            #pragma unroll
            for (int c = 0; c < 8; c++) facc[r][c] = 0.0f;

        // prefetch chunk 0: one uint4 (8 halves) per matrix per thread
        uint4 pa = *(const uint4*)(Ab + (size_t)lrow * C + lq * 8);
        uint4 pb = *(const uint4*)(Bb + (size_t)lrow * C + lq * 8);

        for (int k0 = 0; k0 < C; k0 += 32) {
            __syncthreads();
            {
                const __half2* ap = (const __half2*)&pa;
                const __half2* bp = (const __half2*)&pb;
                #pragma unroll
                for (int m = 0; m < 4; m++) {
                    As[lrow * LDH + lq * 4 + m] = ap[m];   // A: [row][kk]
                    Bs[lrow * LDH + lq * 4 + m] = bp[m];   // B: [col][kk]
                }
            }
            __syncthreads();

            if (k0 + 32 < C) {
                pa = *(const uint4*)(Ab + (size_t)lrow * C + k0 + 32 + lq * 8);
                pb = *(const uint4*)(Bb + (size_t)lrow * C + k0 + 32 + lq * 8);
            }

            __half2 hacc[4][8];
            #pragma unroll
            for (int r = 0; r < 4; r++)
                #pragma unroll
                for (int c = 0; c < 8; c++) hacc[r][c] = __float2half2_rn(0.0f);

            #pragma unroll
            for (int kp = 0; kp < 8; kp++) {
                __half2 a0[4], a1[4], b0[8], b1[8];
                #pragma unroll
                for (int r = 0; r < 4; r++) {
                    uint2 av = *(const uint2*)&As[(ty * 4 + r) * LDH + 2 * kp];
                    a0[r] = *(__half2*)&av.x; a1[r] = *(__half2*)&av.y;
                }
                #pragma unroll
                for (int c = 0; c < 8; c++) {
                    uint2 bv = *(const uint2*)&Bs[(tx + 16 * c) * LDH + 2 * kp];
                    b0[c] = *(__half2*)&bv.x; b1[c] = *(__half2*)&bv.y;
                }
                #pragma unroll
                for (int r = 0; r < 4; r++)
                    #pragma unroll
                    for (int c = 0; c < 8; c++) {
                        hacc[r][c] = __hadd2(hacc[r][c], __hmin2(a0[r], b0[c]));
                        hacc[r][c] = __hadd2(hacc[r][c], __hmin2(a1[r], b1[c]));
                    }
            }

            // flush fp16 partials to fp32 (once per 32 k's)
            #pragma unroll
            for (int r = 0; r < 4; r++)
                #pragma unroll
                for (int c = 0; c < 8; c++)
                    facc[r][c] += __low2float(hacc[r][c]) + __high2float(hacc[r][c]);
        }

        // epilogue: W = 2 - 2S, K = exp(-10W)
        #pragma unroll
        for (int r = 0; r < 4; r++) {
            int row = bi * 128 + ty * 4 + r;
            size_t base = (size_t)row * B + bj * 128;
            #pragma unroll
            for (int c = 0; c < 8; c++) {
                int col = tx + 16 * c;
                float wv = 2.0f - 2.0f * facc[r][c];
                g_W[base + col] = wv;
                g_K[base + col] = __expf(-EPS_INV * wv);
            }
        }
    }
}

// ---------------- persistent Sinkhorn (SMEM-resident K rows) + loss ----------
__device__ __forceinline__ void grid_barrier(int slot) {
    __syncthreads();
    if (threadIdx.x == 0) {
        __threadfence();
        atomicAdd(&g_bar[slot], 1);
        while (*((volatile int*)&g_bar[slot]) < PBLK) { }
        __threadfence();
    }
    __syncthreads();
}

__global__ __launch_bounds__(STHR) void sinkhorn_kernel() {
    extern __shared__ float smem[];
    float* Ks   = smem;                 // [RPB][B] owned K rows, 128 KB
    float* bsm  = smem + RPB * B;       // [B]
    float* avec = bsm + B;              // [RPB] (padded to 32)
    float* red  = avec + 32;            // [STHR]

    int tid = threadIdx.x, w = tid >> 5, lane = tid & 31;
    int blk = blockIdx.x;

    {
        const float4* src = (const float4*)(g_K + (size_t)(blk * RPB) * B);
        float4* dst = (float4*)Ks;
        #pragma unroll
        for (int q = 0; q < (RPB * B / 4) / STHR; q++)
            dst[tid + q * STHR] = src[tid + q * STHR];
        #pragma unroll
        for (int q = 0; q < B / STHR; q++) bsm[tid + q * STHR] = 1.0f;
    }
    __syncthreads();

    int bar = 0;
    for (int it = 0; it < N_ITERS; it++) {
        // Phase A: a_i = 1/(K_i . b), warp per owned row
        {
            const float4* Kr = (const float4*)(Ks + (size_t)w * B);
            const float4* bv = (const float4*)bsm;
            float s = 0.0f;
            #pragma unroll
            for (int q = 0; q < 16; q++) {
                float4 k = Kr[q * 32 + lane];
                float4 v = bv[q * 32 + lane];
                s += k.x * v.x + k.y * v.y + k.z * v.z + k.w * v.w;
            }
            #pragma unroll
            for (int o = 16; o > 0; o >>= 1) s += __shfl_down_sync(0xffffffffu, s, o);
            if (lane == 0) avec[w] = __fdividef(1.0f, s);
        }
        __syncthreads();

        // Phase B: partial column sums over owned rows
        {
            float4 acc = make_float4(0.f, 0.f, 0.f, 0.f);
            #pragma unroll
            for (int i = 0; i < RPB; i++) {
                float4 k = ((const float4*)(Ks + (size_t)i * B))[tid];
                float ai = avec[i];
                acc.x += k.x * ai; acc.y += k.y * ai; acc.z += k.z * ai; acc.w += k.w * ai;
            }
            ((float4*)(g_part + (size_t)blk * B))[tid] = acc;
        }
        grid_barrier(bar++);

        // Phase C: b_j = 1/sum_p part[p][j] for owned 16 cols
        {
            int c  = tid & 15;
            int pg = tid >> 4;
            int j  = blk * RPB + c;
            float s = 0.0f;
            #pragma unroll
            for (int p = 0; p < 4; p++)
                s += g_part[(size_t)(pg * 4 + p) * B + j];
            red[pg * 16 + c] = s;
            __syncthreads();
            #pragma unroll
            for (int off = 16; off > 0; off >>= 1) {
                if (pg < off) red[pg * 16 + c] += red[(pg + off) * 16 + c];
                __syncthreads();
            }
            if (pg == 0) g_b[j] = __fdividef(1.0f, red[c]);
        }
        grid_barrier(bar++);

        #pragma unroll
        for (int q = 0; q < B / STHR; q++) bsm[tid + q * STHR] = g_b[tid + q * STHR];
        __syncthreads();
    }

    // Loss: lp[row] = a_row * sum_j Ks*W*b, warp per owned row
    {
        int row = blk * RPB + w;
        const float4* Kr = (const float4*)(Ks + (size_t)w * B);
        const float4* Wr = (const float4*)(g_W + (size_t)row * B);
        const float4* bv = (const float4*)bsm;
        float s = 0.0f;
        #pragma unroll
        for (int q = 0; q < 16; q++) {
            float4 k  = Kr[q * 32 + lane];
            float4 wv = Wr[q * 32 + lane];
            float4 v  = bv[q * 32 + lane];
            s += k.x * wv.x * v.x + k.y * wv.y * v.y + k.z * wv.z * v.z + k.w * wv.w * v.w;
        }
        #pragma unroll
        for (int o = 16; o > 0; o >>= 1) s += __shfl_down_sync(0xffffffffu, s, o);
        if (lane == 0) g_lp[row] = avec[w] * s;
    }
}

__global__ __launch_bounds__(256) void loss_final_kernel(float* __restrict__ out) {
    __shared__ float sm[8];
    int tid = threadIdx.x;
    float s = 0.0f;
    #pragma unroll
    for (int l = 0; l < 8; l++) s += g_lp[tid + l * 256];
    #pragma unroll
    for (int o = 16; o > 0; o >>= 1) s += __shfl_down_sync(0xffffffffu, s, o);
    int lane = tid & 31, w = tid >> 5;
    if (lane == 0) sm[w] = s;
    __syncthreads();
    if (w == 0) {
        s = (lane < 8) ? sm[lane] : 0.0f;
        #pragma unroll
        for (int o = 4; o > 0; o >>= 1) s += __shfl_down_sync(0xffu, s, o);
        if (lane == 0) out[0] = LOSS_SCALE * s;
    }
}

// ---------------- launcher ---------------------------------------------------
#define SINK_SMEM ((RPB * B + B + 32 + STHR) * (int)sizeof(float))

extern "C" void kernel_launch(void* const* d_in, const int* in_sizes, int n_in,
                              void* d_out, int out_size) {
    const float* ys = (const float*)d_in[0];
    const float* yt = (const float*)d_in[1];
    float* out = (float*)d_out;

    static int smem_set = 0;
    if (!smem_set) {
        cudaFuncSetAttribute(sinkhorn_kernel,
                             cudaFuncAttributeMaxDynamicSharedMemorySize, SINK_SMEM);
        smem_set = 1;
    }

    softmax_kernel<<<2 * B, 256>>>(ys, yt);
    zero_bar_kernel<<<1, 64>>>();
    cdist_kernel<<<PBLK, 512>>>();
    sinkhorn_kernel<<<PBLK, STHR, SINK_SMEM>>>();
    loss_final_kernel<<<1, 256>>>(out);
}

// round 13
// speedup vs baseline: 1.7979x; 1.0646x over previous
#include <cuda_runtime.h>
#include <cuda_fp16.h>

#define B 2048
#define C 1024
#define TEMP_INV 0.5f
#define EPS_INV 10.0f
#define N_ITERS 20
#define LOSS_SCALE 0.001f
#define KSCALE 16384.0f     // 2^14: K' = KSCALE*exp(-10W) stays normal in fp16
#define PBLK 128            // persistent blocks, all co-resident (< 148 SMs)
#define RPB (B / PBLK)      // 16 rows/cols owned per block
#define STHR 512

typedef unsigned int u32;

// ---------------- scratch (device globals; no runtime allocation) -----------
__device__ __half g_psh[B * C];
__device__ __half g_pth[B * C];
__device__ float  g_W [B * B];
__device__ __half g_Kh[B * B];       // K' fp16 (scaled)
__device__ float  g_b [B];
__device__ float  g_lp[B];
__device__ float  g_part[B * PBLK];  // col-major: [col][block]
__device__ int    g_bar[512];        // 8 counters per barrier slot

// packed u16 min == packed fp16 min for non-negative halves (bit-monotonic)
__device__ __forceinline__ __half2 hmin2p(__half2 a, __half2 b) {
    u32 r, x = *(u32*)&a, y = *(u32*)&b;
    asm("min.u16x2 %0, %1, %2;" : "=r"(r) : "r"(x), "r"(y));
    return *(__half2*)&r;
}

// ---------------- softmax: one block per row (4096 rows), fp16 out ----------
__global__ __launch_bounds__(256) void softmax_kernel(const float* __restrict__ ys,
                                                      const float* __restrict__ yt) {
    int row = blockIdx.x;
    const float* src = (row < B) ? (ys + (size_t)row * C) : (yt + (size_t)(row - B) * C);
    __half*      dst = (row < B) ? (g_psh + (size_t)row * C) : (g_pth + (size_t)(row - B) * C);
    int tid = threadIdx.x;

    float4 x = ((const float4*)src)[tid];
    x.x *= TEMP_INV; x.y *= TEMP_INV; x.z *= TEMP_INV; x.w *= TEMP_INV;

    __shared__ float smx[8];
    __shared__ float bc;

    float m = fmaxf(fmaxf(x.x, x.y), fmaxf(x.z, x.w));
    #pragma unroll
    for (int o = 16; o > 0; o >>= 1) m = fmaxf(m, __shfl_down_sync(0xffffffffu, m, o));
    int lane = tid & 31, w = tid >> 5;
    if (lane == 0) smx[w] = m;
    __syncthreads();
    if (w == 0) {
        m = (lane < 8) ? smx[lane] : -1e30f;
        #pragma unroll
        for (int o = 4; o > 0; o >>= 1) m = fmaxf(m, __shfl_down_sync(0xffu, m, o));
        if (lane == 0) bc = m;
    }
    __syncthreads();
    m = bc;

    float4 e;
    e.x = __expf(x.x - m); e.y = __expf(x.y - m);
    e.z = __expf(x.z - m); e.w = __expf(x.w - m);
    float s = (e.x + e.y) + (e.z + e.w);

    #pragma unroll
    for (int o = 16; o > 0; o >>= 1) s += __shfl_down_sync(0xffffffffu, s, o);
    __syncthreads();
    if (lane == 0) smx[w] = s;
    __syncthreads();
    if (w == 0) {
        s = (lane < 8) ? smx[lane] : 0.0f;
        #pragma unroll
        for (int o = 4; o > 0; o >>= 1) s += __shfl_down_sync(0xffu, s, o);
        if (lane == 0) bc = s;
    }
    __syncthreads();
    float inv = __fdividef(1.0f, bc);

    ((__half2*)dst)[2 * tid]     = __floats2half2_rn(e.x * inv, e.y * inv);
    ((__half2*)dst)[2 * tid + 1] = __floats2half2_rn(e.z * inv, e.w * inv);
}

__global__ void zero_bar_kernel() {
    g_bar[threadIdx.x] = 0;
}

// ---------------- cdist via min-identity, dual-pipe fp16 ---------------------
// W = 2 - 2*sum_k min(p,q); VIMNMX(alu) + HADD2(fma).
#define LDH 18

__global__ __launch_bounds__(512) void cdist_kernel() {
    __shared__ __half2 As[128 * LDH];
    __shared__ __half2 Bs[128 * LDH];

    int tid = threadIdx.x;
    int tx = tid & 15, ty = tid >> 4;
    int lrow = tid >> 2, lq = tid & 3;

    #pragma unroll 1
    for (int s = 0; s < 2; s++) {
        int t  = blockIdx.x * 2 + s;
        int bi = t >> 4, bj = t & 15;
        const __half* Ab = g_psh + (size_t)(bi * 128) * C;
        const __half* Bb = g_pth + (size_t)(bj * 128) * C;

        float facc[4][8];
        #pragma unroll
        for (int r = 0; r < 4; r++)
            #pragma unroll
            for (int c = 0; c < 8; c++) facc[r][c] = 0.0f;

        uint4 pa = *(const uint4*)(Ab + (size_t)lrow * C + lq * 8);
        uint4 pb = *(const uint4*)(Bb + (size_t)lrow * C + lq * 8);

        for (int k0 = 0; k0 < C; k0 += 32) {
            __syncthreads();
            {
                const __half2* ap = (const __half2*)&pa;
                const __half2* bp = (const __half2*)&pb;
                #pragma unroll
                for (int m = 0; m < 4; m++) {
                    As[lrow * LDH + lq * 4 + m] = ap[m];
                    Bs[lrow * LDH + lq * 4 + m] = bp[m];
                }
            }
            __syncthreads();

            if (k0 + 32 < C) {
                pa = *(const uint4*)(Ab + (size_t)lrow * C + k0 + 32 + lq * 8);
                pb = *(const uint4*)(Bb + (size_t)lrow * C + k0 + 32 + lq * 8);
            }

            __half2 hacc[4][8];
            #pragma unroll
            for (int r = 0; r < 4; r++)
                #pragma unroll
                for (int c = 0; c < 8; c++) hacc[r][c] = __float2half2_rn(0.0f);

            #pragma unroll
            for (int kp = 0; kp < 8; kp++) {
                __half2 a0[4], a1[4], b0[8], b1[8];
                #pragma unroll
                for (int r = 0; r < 4; r++) {
                    uint2 av = *(const uint2*)&As[(ty * 4 + r) * LDH + 2 * kp];
                    a0[r] = *(__half2*)&av.x; a1[r] = *(__half2*)&av.y;
                }
                #pragma unroll
                for (int c = 0; c < 8; c++) {
                    uint2 bv = *(const uint2*)&Bs[(tx + 16 * c) * LDH + 2 * kp];
                    b0[c] = *(__half2*)&bv.x; b1[c] = *(__half2*)&bv.y;
                }
                #pragma unroll
                for (int r = 0; r < 4; r++)
                    #pragma unroll
                    for (int c = 0; c < 8; c++) {
                        hacc[r][c] = __hadd2(hacc[r][c], hmin2p(a0[r], b0[c]));
                        hacc[r][c] = __hadd2(hacc[r][c], hmin2p(a1[r], b1[c]));
                    }
            }

            #pragma unroll
            for (int r = 0; r < 4; r++)
                #pragma unroll
                for (int c = 0; c < 8; c++)
                    facc[r][c] += __low2float(hacc[r][c]) + __high2float(hacc[r][c]);
        }

        // epilogue: W = 2 - 2S (fp32), K' = KSCALE*exp(-10W) (fp16)
        #pragma unroll
        for (int r = 0; r < 4; r++) {
            int row = bi * 128 + ty * 4 + r;
            size_t base = (size_t)row * B + bj * 128;
            #pragma unroll
            for (int c = 0; c < 8; c++) {
                int col = tx + 16 * c;
                float wv = 2.0f - 2.0f * facc[r][c];
                g_W[base + col]  = wv;
                g_Kh[base + col] = __float2half(KSCALE * __expf(-EPS_INV * wv));
            }
        }
    }
}

// ---------------- persistent Sinkhorn (fp16 K in SMEM, fused passes) ---------
__device__ __forceinline__ void grid_barrier(int slot) {
    __syncthreads();
    if (threadIdx.x == 0) {
        __threadfence();
        atomicAdd(&g_bar[slot * 8 + (blockIdx.x & 7)], 1);
    }
    if (threadIdx.x < 8) {
        while (((volatile int*)g_bar)[slot * 8 + threadIdx.x] < (PBLK / 8)) { }
    }
    __syncthreads();
}

__global__ __launch_bounds__(STHR) void sinkhorn_kernel() {
    extern __shared__ float smem[];
    __half2* Ksh = (__half2*)smem;               // [RPB][B/2] = 64 KB
    float*   bsm = smem + (RPB * B / 2) / 1;     // after 64KB = 16384 floats
    // layout: Ksh occupies 16384 floats worth; bsm next
    bsm = smem + RPB * B / 2;                    // 16384 floats offset
    float* red  = bsm + B;                       // [16*512] = 32 KB
    float* avec = red + 16 * STHR;               // [32]

    int tid = threadIdx.x, w = tid >> 5, lane = tid & 31;
    int blk = blockIdx.x;

    // preload owned K' rows (64 KB) + init b = 1
    {
        const uint4* src = (const uint4*)(g_Kh + (size_t)(blk * RPB) * B);
        uint4* dst = (uint4*)Ksh;
        #pragma unroll
        for (int q = 0; q < (RPB * B / 8) / STHR; q++)
            dst[tid + q * STHR] = src[tid + q * STHR];
        #pragma unroll
        for (int q = 0; q < B / STHR; q++) bsm[tid + q * STHR] = 1.0f;
    }
    __syncthreads();

    // thread owns 4 columns j = tid*4..+3 of the owned row-block
    uint2 kreg[RPB];
    #pragma unroll
    for (int i = 0; i < RPB; i++)
        kreg[i] = *(const uint2*)&Ksh[i * (B / 2) + tid * 2];

    int slot = 0;
    for (int it = 0; it < N_ITERS; it++) {
        // Phase A: partial row-dots from owned columns
        {
            float4 b4 = ((const float4*)bsm)[tid];
            #pragma unroll
            for (int i = 0; i < RPB; i++) {
                float2 lo = __half22float2(*(__half2*)&kreg[i].x);
                float2 hi = __half22float2(*(__half2*)&kreg[i].y);
                red[i * STHR + tid] = lo.x * b4.x + lo.y * b4.y + hi.x * b4.z + hi.y * b4.w;
            }
        }
        __syncthreads();
        // reduce: warp w sums row w's 512 partials -> avec[w] = 1/rowsum
        {
            float s = 0.0f;
            #pragma unroll
            for (int q = 0; q < 4; q++) {
                float4 v = *(const float4*)&red[w * STHR + q * 128 + lane * 4];
                s += (v.x + v.y) + (v.z + v.w);
            }
            #pragma unroll
            for (int o = 16; o > 0; o >>= 1) s += __shfl_down_sync(0xffffffffu, s, o);
            if (lane == 0) avec[w] = __fdividef(1.0f, s);
        }
        __syncthreads();

        // Phase B: partial column sums (zero LDS for K — reuse kreg)
        {
            float4 acc = make_float4(0.f, 0.f, 0.f, 0.f);
            #pragma unroll
            for (int i = 0; i < RPB; i++) {
                float ai = avec[i];
                float2 lo = __half22float2(*(__half2*)&kreg[i].x);
                float2 hi = __half22float2(*(__half2*)&kreg[i].y);
                acc.x += lo.x * ai; acc.y += lo.y * ai;
                acc.z += hi.x * ai; acc.w += hi.y * ai;
            }
            int j = tid * 4;
            g_part[(size_t)(j + 0) * PBLK + blk] = acc.x;
            g_part[(size_t)(j + 1) * PBLK + blk] = acc.y;
            g_part[(size_t)(j + 2) * PBLK + blk] = acc.z;
            g_part[(size_t)(j + 3) * PBLK + blk] = acc.w;
        }
        grid_barrier(slot++);

        // Phase C: warp per owned col; coalesced ldcg of 128 partials
        {
            int j = blk * RPB + w;
            float4 v = __ldcg((const float4*)(g_part + (size_t)j * PBLK) + lane);
            float s = (v.x + v.y) + (v.z + v.w);
            #pragma unroll
            for (int o = 16; o > 0; o >>= 1) s += __shfl_down_sync(0xffffffffu, s, o);
            if (lane == 0) g_b[j] = __fdividef(1.0f, s);
        }
        grid_barrier(slot++);

        // reload full b (L2-coherent)
        #pragma unroll
        for (int q = 0; q < B / (STHR * 4); q++) {
            float4 v = __ldcg((const float4*)g_b + tid + q * STHR);
            *(float4*)&bsm[(tid + q * STHR) * 4] = v;
        }
        __syncthreads();
    }

    // Loss: lp[row] = a_row * sum_j K'*W*b, warp per owned row
    {
        int row = blk * RPB + w;
        float s = 0.0f;
        #pragma unroll
        for (int q = 0; q < 16; q++) {
            int j = q * 128 + lane * 4;
            uint2 kv = *(const uint2*)&Ksh[w * (B / 2) + j / 2];
            float2 lo = __half22float2(*(__half2*)&kv.x);
            float2 hi = __half22float2(*(__half2*)&kv.y);
            float4 wv = __ldg((const float4*)(g_W + (size_t)row * B + j));
            float4 bv = *(const float4*)&bsm[j];
            s += lo.x * wv.x * bv.x + lo.y * wv.y * bv.y
               + hi.x * wv.z * bv.z + hi.y * wv.w * bv.w;
        }
        #pragma unroll
        for (int o = 16; o > 0; o >>= 1) s += __shfl_down_sync(0xffffffffu, s, o);
        if (lane == 0) g_lp[row] = avec[w] * s;
    }
}

__global__ __launch_bounds__(256) void loss_final_kernel(float* __restrict__ out) {
    __shared__ float sm[8];
    int tid = threadIdx.x;
    float s = 0.0f;
    #pragma unroll
    for (int l = 0; l < 8; l++) s += g_lp[tid + l * 256];
    #pragma unroll
    for (int o = 16; o > 0; o >>= 1) s += __shfl_down_sync(0xffffffffu, s, o);
    int lane = tid & 31, w = tid >> 5;
    if (lane == 0) sm[w] = s;
    __syncthreads();
    if (w == 0) {
        s = (lane < 8) ? sm[lane] : 0.0f;
        #pragma unroll
        for (int o = 4; o > 0; o >>= 1) s += __shfl_down_sync(0xffu, s, o);
        if (lane == 0) out[0] = LOSS_SCALE * s;
    }
}

// ---------------- launcher ---------------------------------------------------
// smem floats: K' 16384 + b 2048 + red 8192 + avec 32
#define SINK_SMEM ((RPB * B / 2 + B + 16 * STHR + 32) * (int)sizeof(float))

extern "C" void kernel_launch(void* const* d_in, const int* in_sizes, int n_in,
                              void* d_out, int out_size) {
    const float* ys = (const float*)d_in[0];
    const float* yt = (const float*)d_in[1];
    float* out = (float*)d_out;

    static int smem_set = 0;
    if (!smem_set) {
        cudaFuncSetAttribute(sinkhorn_kernel,
                             cudaFuncAttributeMaxDynamicSharedMemorySize, SINK_SMEM);
        smem_set = 1;
    }

    softmax_kernel<<<2 * B, 256>>>(ys, yt);
    zero_bar_kernel<<<1, 512>>>();
    cdist_kernel<<<PBLK, 512>>>();
    sinkhorn_kernel<<<PBLK, STHR, SINK_SMEM>>>();
    loss_final_kernel<<<1, 256>>>(out);
}